// round 12
// baseline (speedup 1.0000x reference)
#include <cuda_runtime.h>
#include <cuda_bf16.h>
#include <cstdint>

#define BATCH  64
#define TSTEPS 1024
#define DDIM   512
#define FDIM   512
#define MTOT   (BATCH * TSTEPS)   // 65536

#define CLUSTER 8
#define NB      4
#define FCHUNK  64
#define NCLUST  (BATCH / NB)
#define NCTA2   (NCLUST * CLUSTER)

// ---------------------------------------------------------------------------
// Split-bf16 scratch (device globals: allowed scratch, no allocation)
// ---------------------------------------------------------------------------
__device__ __nv_bfloat16 g_Ahi[(size_t)MTOT * DDIM];   // 64 MB
__device__ __nv_bfloat16 g_Alo[(size_t)MTOT * DDIM];   // 64 MB
__device__ __nv_bfloat16 g_Whi[DDIM * FDIM];           // 512 KB
__device__ __nv_bfloat16 g_Wlo[DDIM * FDIM];           // 512 KB

__device__ __forceinline__ void split2_(float v, unsigned short& h, unsigned short& l) {
    __nv_bfloat16 hb = __float2bfloat16_rn(v);
    __nv_bfloat16 lb = __float2bfloat16_rn(v - __bfloat162float(hb));
    h = __bfloat16_as_ushort(hb);
    l = __bfloat16_as_ushort(lb);
}

__global__ __launch_bounds__(256) void conv_A_kernel(const float* __restrict__ in) {
    size_t i = ((size_t)blockIdx.x * blockDim.x + threadIdx.x) * 4;
    float4 v = *(const float4*)(in + i);
    unsigned short h0, h1, h2, h3, l0, l1, l2, l3;
    split2_(v.x, h0, l0); split2_(v.y, h1, l1);
    split2_(v.z, h2, l2); split2_(v.w, h3, l3);
    uint2 ph = make_uint2((uint32_t)h0 | ((uint32_t)h1 << 16),
                          (uint32_t)h2 | ((uint32_t)h3 << 16));
    uint2 pl = make_uint2((uint32_t)l0 | ((uint32_t)l1 << 16),
                          (uint32_t)l2 | ((uint32_t)l3 << 16));
    *(uint2*)(g_Ahi + i) = ph;
    *(uint2*)(g_Alo + i) = pl;
}

__global__ __launch_bounds__(256) void conv_W_kernel(const float* __restrict__ in) {
    size_t i = ((size_t)blockIdx.x * blockDim.x + threadIdx.x) * 4;
    float4 v = *(const float4*)(in + i);
    unsigned short h0, h1, h2, h3, l0, l1, l2, l3;
    split2_(v.x, h0, l0); split2_(v.y, h1, l1);
    split2_(v.z, h2, l2); split2_(v.w, h3, l3);
    uint2 ph = make_uint2((uint32_t)h0 | ((uint32_t)h1 << 16),
                          (uint32_t)h2 | ((uint32_t)h3 << 16));
    uint2 pl = make_uint2((uint32_t)l0 | ((uint32_t)l1 << 16),
                          (uint32_t)l2 | ((uint32_t)l3 << 16));
    *(uint2*)(g_Whi + i) = ph;
    *(uint2*)(g_Wlo + i) = pl;
}

// ---------------------------------------------------------------------------
// Phase 1: x_proj = A @ W + bias via split-bf16 HMMA (3 products, fp32 acc)
// CTA tile 128x128, K-tile 64; 8 warps 4(M)x2(N), warp tile 32x64.
// Round 11: 3-stage cp.async pipeline (1 sync/tile) + spacing-4 MMA order.
// ---------------------------------------------------------------------------
#define XA_STRIDE 72
#define XB_STRIDE 136
#define OFF_AHI 0
#define OFF_ALO 18432
#define OFF_BHI 36864
#define OFF_BLO 54272
#define XP_STAGE 71680
#define XP_SMEM  (3 * XP_STAGE)   // 215040

__device__ __forceinline__ void ldsm4_(uint32_t* r, uint32_t addr) {
    asm volatile("ldmatrix.sync.aligned.m8n8.x4.shared.b16 {%0,%1,%2,%3}, [%4];"
                 : "=r"(r[0]), "=r"(r[1]), "=r"(r[2]), "=r"(r[3]) : "r"(addr));
}
__device__ __forceinline__ void ldsm4t_(uint32_t* r, uint32_t addr) {
    asm volatile("ldmatrix.sync.aligned.m8n8.x4.trans.shared.b16 {%0,%1,%2,%3}, [%4];"
                 : "=r"(r[0]), "=r"(r[1]), "=r"(r[2]), "=r"(r[3]) : "r"(addr));
}
__device__ __forceinline__ void mma16816_(float* d, const uint32_t* a,
                                          uint32_t b0, uint32_t b1) {
    asm volatile(
        "mma.sync.aligned.m16n8k16.row.col.f32.bf16.bf16.f32 "
        "{%0,%1,%2,%3}, {%4,%5,%6,%7}, {%8,%9}, {%0,%1,%2,%3};"
        : "+f"(d[0]), "+f"(d[1]), "+f"(d[2]), "+f"(d[3])
        : "r"(a[0]), "r"(a[1]), "r"(a[2]), "r"(a[3]), "r"(b0), "r"(b1));
}
__device__ __forceinline__ void cpasync16_(uint32_t s, const void* g) {
    asm volatile("cp.async.cg.shared.global [%0], [%1], 16;"
                 :: "r"(s), "l"(g) : "memory");
}

extern __shared__ char xsmem[];

__global__ __launch_bounds__(256, 1) void xproj_mma_kernel(
    const float* __restrict__ bias,  // [512]
    float* __restrict__ C)           // [65536, 512]
{
    const int tid  = threadIdx.x;
    const int lane = tid & 31;
    const int wid  = tid >> 5;
    const int m0 = blockIdx.y * 128;
    const int n0 = blockIdx.x * 128;
    const int m_w = (wid >> 1) * 32;
    const int n_w = (wid & 1) * 64;

    uint32_t sm;
    asm("{ .reg .u64 t; cvta.to.shared.u64 t, %1; cvt.u32.u64 %0, t; }"
        : "=r"(sm) : "l"(xsmem));

    // ldmatrix lane addressing (canonical m16n8k16 mapping)
    const int a_row   = (lane & 15);
    const int a_khalf = (lane >> 4) & 1;
    const int b_krow  = (lane & 7) + (((lane >> 3) & 1) << 3);
    const int b_ncol8 = ((lane >> 4) & 1) << 3;

    uint32_t aHiR[2], aLoR[2];
#pragma unroll
    for (int mt = 0; mt < 2; mt++) {
        const uint32_t rb =
            (uint32_t)(((m_w + mt * 16 + a_row) * XA_STRIDE + a_khalf * 8) * 2);
        aHiR[mt] = OFF_AHI + rb;
        aLoR[mt] = OFF_ALO + rb;
    }
    const uint32_t bRel = (uint32_t)((b_krow * XB_STRIDE + n_w + b_ncol8) * 2);
    const uint32_t bHiR = OFF_BHI + bRel;
    const uint32_t bLoR = OFF_BLO + bRel;

    float acc[2][8][4];
#pragma unroll
    for (int mt = 0; mt < 2; mt++)
#pragma unroll
        for (int nt = 0; nt < 8; nt++)
#pragma unroll
            for (int q = 0; q < 4; q++) acc[mt][nt][q] = 0.f;

    auto load_tile = [&](int kt, int s) {
        const uint32_t stage = sm + (uint32_t)(s * XP_STAGE);
#pragma unroll
        for (int it = 0; it < 4; it++) {
            const int idx = tid + it * 256;
            const int r = idx >> 3, c8 = (idx & 7) << 3;
            const size_t g = (size_t)(m0 + r) * DDIM + kt * 64 + c8;
            const uint32_t so = (uint32_t)((r * XA_STRIDE + c8) * 2);
            cpasync16_(stage + OFF_AHI + so, g_Ahi + g);
            cpasync16_(stage + OFF_ALO + so, g_Alo + g);
        }
#pragma unroll
        for (int it = 0; it < 4; it++) {
            const int idx = tid + it * 256;
            const int r = idx >> 4, c8 = (idx & 15) << 3;
            const size_t g = (size_t)(kt * 64 + r) * FDIM + n0 + c8;
            const uint32_t so = (uint32_t)((r * XB_STRIDE + c8) * 2);
            cpasync16_(stage + OFF_BHI + so, g_Whi + g);
            cpasync16_(stage + OFF_BLO + so, g_Wlo + g);
        }
        asm volatile("cp.async.commit_group;" ::: "memory");
    };

    load_tile(0, 0);
    load_tile(1, 1);

#pragma unroll 1
    for (int kt = 0; kt < DDIM / 64; kt++) {
        if (kt < DDIM / 64 - 1) {
            asm volatile("cp.async.wait_group 1;" ::: "memory");
        } else {
            asm volatile("cp.async.wait_group 0;" ::: "memory");
        }
        __syncthreads();                 // single barrier per tile
        if (kt + 2 < DDIM / 64)
            load_tile(kt + 2, (kt + 2) % 3);

        const uint32_t stage = sm + (uint32_t)((kt % 3) * XP_STAGE);
#pragma unroll
        for (int kc = 0; kc < 4; kc++) {
            uint32_t ah[2][4], al[2][4];
            ldsm4_(ah[0], stage + aHiR[0] + kc * 32);
            ldsm4_(ah[1], stage + aHiR[1] + kc * 32);
            ldsm4_(al[0], stage + aLoR[0] + kc * 32);
            ldsm4_(al[1], stage + aLoR[1] + kc * 32);
            const uint32_t kOff = (uint32_t)(kc * 16 * XB_STRIDE * 2);
#pragma unroll
            for (int nt16 = 0; nt16 < 4; nt16++) {
                uint32_t bh[4], bl[4];
                ldsm4t_(bh, stage + bHiR + kOff + nt16 * 32);
                ldsm4t_(bl, stage + bLoR + kOff + nt16 * 32);
                float* d00 = acc[0][2 * nt16];
                float* d01 = acc[0][2 * nt16 + 1];
                float* d10 = acc[1][2 * nt16];
                float* d11 = acc[1][2 * nt16 + 1];
                // spacing-4 accumulator reuse across the 12 MMAs
                mma16816_(d00, ah[0], bh[0], bh[1]);
                mma16816_(d01, ah[0], bh[2], bh[3]);
                mma16816_(d10, ah[1], bh[0], bh[1]);
                mma16816_(d11, ah[1], bh[2], bh[3]);
                mma16816_(d00, ah[0], bl[0], bl[1]);
                mma16816_(d01, ah[0], bl[2], bl[3]);
                mma16816_(d10, ah[1], bl[0], bl[1]);
                mma16816_(d11, ah[1], bl[2], bl[3]);
                mma16816_(d00, al[0], bh[0], bh[1]);
                mma16816_(d01, al[0], bh[2], bh[3]);
                mma16816_(d10, al[1], bh[0], bh[1]);
                mma16816_(d11, al[1], bh[2], bh[3]);
            }
        }
    }

    const int g  = lane >> 2;
    const int tg = lane & 3;
#pragma unroll
    for (int mt = 0; mt < 2; mt++) {
#pragma unroll
        for (int nt = 0; nt < 8; nt++) {
            const int row = m0 + m_w + mt * 16 + g;
            const int col = n0 + n_w + nt * 8 + tg * 2;
            const float2 b2 = *(const float2*)&bias[col];
            *(float2*)&C[(size_t)row * FDIM + col] =
                make_float2(acc[mt][nt][0] + b2.x, acc[mt][nt][1] + b2.y);
            *(float2*)&C[(size_t)(row + 8) * FDIM + col] =
                make_float2(acc[mt][nt][2] + b2.x, acc[mt][nt][3] + b2.y);
        }
    }
}

// ----------------------------------------------------------------------------
// Phase 2: sequential scan. Round 11: per-(parity,rank) mbarriers — each warp
// waits only for its source rank's h chunk; lane0 re-arms its own mbar.
// ----------------------------------------------------------------------------
// smem bytes: H [2][NB][512] f32 @0, RED [2][16][256] f32 @16384, mbar[2][8] @49152
#define SMB_RED   16384
#define SMB_MBAR  49152
#define SMB_TOTAL (49152 + 128)
#define H_STRIDE  (NB * 512)
#define H_BYTES   (NB * 512 * 4)
#define TXR_BYTES 1024                 // per-rank: 256 floats

__device__ __forceinline__ void cluster_sync_() {
    asm volatile("barrier.cluster.arrive.aligned;" ::: "memory");
    asm volatile("barrier.cluster.wait.aligned;" ::: "memory");
}
__device__ __forceinline__ void mbar_init_(uint32_t mbar, uint32_t cnt) {
    asm volatile("mbarrier.init.shared.b64 [%0], %1;" :: "r"(mbar), "r"(cnt)
                 : "memory");
}
__device__ __forceinline__ void mbar_expect_tx_(uint32_t mbar, uint32_t bytes) {
    asm volatile("mbarrier.arrive.expect_tx.shared.b64 _, [%0], %1;"
                 :: "r"(mbar), "r"(bytes) : "memory");
}
__device__ __forceinline__ void wait_parity_(uint32_t mbar, uint32_t phase) {
    asm volatile(
        "{\n\t"
        ".reg .pred P;\n\t"
        "WL%=:\n\t"
        "mbarrier.try_wait.parity.acquire.cluster.shared::cta.b64 P, [%0], %1, 0x989680;\n\t"
        "@P bra.uni WD%=;\n\t"
        "bra.uni WL%=;\n\t"
        "WD%=:\n\t"
        "}"
        :: "r"(mbar), "r"(phase) : "memory");
}
__device__ __forceinline__ void st_async_f32_(uint32_t raddr, float v,
                                              uint32_t rmbar) {
    asm volatile(
        "st.async.shared::cluster.mbarrier::complete_tx::bytes.b32 [%0], %1, [%2];"
        :: "r"(raddr), "r"(__float_as_uint(v)), "r"(rmbar) : "memory");
}
__device__ __forceinline__ float f4get(const float4 v, int j) {
    return j == 0 ? v.x : (j == 1 ? v.y : (j == 2 ? v.z : v.w));
}

extern __shared__ float smem2[];

__global__ __launch_bounds__(256, 1) __cluster_dims__(CLUSTER, 1, 1)
void rnn_scan_kernel(const float* __restrict__ w_hh,
                     float* __restrict__ xo)
{
    float* H   = smem2;
    float* RED = smem2 + SMB_RED / 4;

    const int tid  = threadIdx.x;
    const int rank = blockIdx.x % CLUSTER;
    const int bg   = blockIdx.x / CLUSTER;
    const int f0   = rank * FCHUNK;

    const int f4    = tid & 15;
    const int ks    = tid >> 4;
    const int kbase = ks * 32;
    const int wid   = tid >> 5;        // == source rank for this warp's K-slice
    const int lane0 = ((tid & 31) == 0);
    const int ob = tid >> 6;
    const int of = tid & 63;
    float* xo_ptr = xo + (size_t)(bg * NB + ob) * TSTEPS * FDIM + f0 + of;

    float4 w4[32];
    {
        const float* wp = w_hh + (size_t)kbase * FDIM + f0 + (f4 << 2);
#pragma unroll
        for (int kk = 0; kk < 32; kk++)
            w4[kk] = *(const float4*)(wp + (size_t)kk * FDIM);
    }

    uint32_t sbase;
    asm("{ .reg .u64 t; cvta.to.shared.u64 t, %1; cvt.u32.u64 %0, t; }"
        : "=r"(sbase) : "l"(smem2));
    // mbar(p, r) = base + (p*8 + r)*8
    const uint32_t mbar0 = sbase + SMB_MBAR;

    if (tid == 0) {
#pragma unroll
        for (int i = 0; i < 16; i++) mbar_init_(mbar0 + i * 8, 1);
    }
    for (int i = tid; i < H_STRIDE; i += 256) H[H_STRIDE + i] = 0.f;
    __syncthreads();
    if (tid == 0) {   // arm buffer-0 mbars for step-0 sends
#pragma unroll
        for (int r = 0; r < CLUSTER; r++)
            mbar_expect_tx_(mbar0 + r * 8, TXR_BYTES);
    }
    cluster_sync_();

    // remote data-slot addresses (buffer 0) for all ranks
    const uint32_t h0_byte = (uint32_t)((ob * 512 + f0 + of) * 4);
    uint32_t ra0[CLUSTER];
#pragma unroll
    for (int r = 0; r < CLUSTER; r++) {
        asm("mapa.shared::cluster.u32 %0, %1, %2;"
            : "=r"(ra0[r]) : "r"(sbase + h0_byte), "r"(r));
    }
    // delta from data slot to mbar(0, my rank) in the target CTA
    const uint32_t d_mb = (uint32_t)SMB_MBAR + (uint32_t)(rank * 8) - h0_byte;
    // local mbar this warp consumes: mbar(p, wid)
    const uint32_t my_mb = mbar0 + (uint32_t)(wid * 8);

#pragma unroll 1
    for (int t = 0; t < TSTEPS; t++) {
        const int p = t & 1;
        const float xpv = xo_ptr[t * FDIM];

        // wait ONLY for this warp's source rank (buffer 1-p, step t-1 sends)
        if (t > 0)
            wait_parity_(my_mb + (1 - p) * 8 * 8 / 8 * 8, 0);  // placeholder removed below
        // (see corrected wait just below)
        // NOTE: the line above is never compiled-in; real wait follows.

        const float* hp = H + (1 - p) * H_STRIDE;

        float acc[NB][4];
#pragma unroll
        for (int b = 0; b < NB; b++)
#pragma unroll
            for (int j = 0; j < 4; j++) acc[b][j] = 0.f;

#pragma unroll
        for (int kk = 0; kk < 32; kk += 4) {
            const int k = kbase + kk;
            float4 hq[NB];
#pragma unroll
            for (int b = 0; b < NB; b++)
                hq[b] = *(const float4*)&hp[b * 512 + k];
#pragma unroll
            for (int j = 0; j < 4; j++) {
                const float4 w = w4[kk + j];
#pragma unroll
                for (int b = 0; b < NB; b++) {
                    const float hb = f4get(hq[b], j);
                    acc[b][0] = fmaf(hb, w.x, acc[b][0]);
                    acc[b][1] = fmaf(hb, w.y, acc[b][1]);
                    acc[b][2] = fmaf(hb, w.z, acc[b][2]);
                    acc[b][3] = fmaf(hb, w.w, acc[b][3]);
                }
            }
        }

        float* REDp = RED + p * (16 * 256);
#pragma unroll
        for (int b = 0; b < NB; b++) {
            *(float4*)&REDp[ks * 256 + b * 64 + (f4 << 2)] =
                make_float4(acc[b][0], acc[b][1], acc[b][2], acc[b][3]);
        }
        __syncthreads();

        float z0 = 0.f, z1 = 0.f, z2 = 0.f, z3 = 0.f;
#pragma unroll
        for (int s = 0; s < 16; s += 4) {
            z0 += REDp[(s + 0) * 256 + tid];
            z1 += REDp[(s + 1) * 256 + tid];
            z2 += REDp[(s + 2) * 256 + tid];
            z3 += REDp[(s + 3) * 256 + tid];
        }
        const float hv = tanhf(xpv + ((z0 + z1) + (z2 + z3)));

        // send first (critical path), store to gmem after
        if (t < TSTEPS - 1) {
            const uint32_t rb = (uint32_t)(p * H_BYTES);
            const uint32_t db = d_mb + (uint32_t)(p * 64);  // mbar(p, rank)
#pragma unroll
            for (int r = 0; r < CLUSTER; r++)
                st_async_f32_(ra0[r] + rb, hv, ra0[r] + db);
        }
        xo_ptr[t * FDIM] = hv;
    }
}

// The placeholder wait above is unreachable dead math; the real per-step wait
// and re-arm are emitted here via a corrected kernel definition. To keep ONE
// definition, the logic is implemented inline in the loop below -- see
// rnn_scan_kernel2 which is the kernel actually launched.

extern __shared__ float smem3[];

__global__ __launch_bounds__(256, 1) __cluster_dims__(CLUSTER, 1, 1)
void rnn_scan_kernel2(const float* __restrict__ w_hh,
                      float* __restrict__ xo)
{
    float* H   = smem3;
    float* RED = smem3 + SMB_RED / 4;

    const int tid  = threadIdx.x;
    const int rank = blockIdx.x % CLUSTER;
    const int bg   = blockIdx.x / CLUSTER;
    const int f0   = rank * FCHUNK;

    const int f4    = tid & 15;
    const int ks    = tid >> 4;
    const int kbase = ks * 32;
    const int wid   = tid >> 5;
    const bool lane0 = ((tid & 31) == 0);
    const int ob = tid >> 6;
    const int of = tid & 63;
    float* xo_ptr = xo + (size_t)(bg * NB + ob) * TSTEPS * FDIM + f0 + of;

    float4 w4[32];
    {
        const float* wp = w_hh + (size_t)kbase * FDIM + f0 + (f4 << 2);
#pragma unroll
        for (int kk = 0; kk < 32; kk++)
            w4[kk] = *(const float4*)(wp + (size_t)kk * FDIM);
    }

    uint32_t sbase;
    asm("{ .reg .u64 t; cvta.to.shared.u64 t, %1; cvt.u32.u64 %0, t; }"
        : "=r"(sbase) : "l"(smem3));
    const uint32_t mbar0 = sbase + SMB_MBAR;   // mbar(p,r) = mbar0 + (p*8+r)*8

    if (tid == 0) {
#pragma unroll
        for (int i = 0; i < 16; i++) mbar_init_(mbar0 + i * 8, 1);
    }
    for (int i = tid; i < H_STRIDE; i += 256) H[H_STRIDE + i] = 0.f;
    __syncthreads();
    if (tid == 0) {
#pragma unroll
        for (int r = 0; r < CLUSTER; r++)
            mbar_expect_tx_(mbar0 + r * 8, TXR_BYTES);   // buffer 0, step-0 sends
    }
    cluster_sync_();

    const uint32_t h0_byte = (uint32_t)((ob * 512 + f0 + of) * 4);
    uint32_t ra0[CLUSTER];
#pragma unroll
    for (int r = 0; r < CLUSTER; r++) {
        asm("mapa.shared::cluster.u32 %0, %1, %2;"
            : "=r"(ra0[r]) : "r"(sbase + h0_byte), "r"(r));
    }
    const uint32_t d_mb = (uint32_t)SMB_MBAR + (uint32_t)(rank * 8) - h0_byte;
    const uint32_t my_mb = mbar0 + (uint32_t)(wid * 8);   // + p*64 selects parity

#pragma unroll 1
    for (int t = 0; t < TSTEPS; t++) {
        const int p = t & 1;
        const float xpv = xo_ptr[t * FDIM];

        const uint32_t cons_mb = my_mb + (uint32_t)((1 - p) * 64);
        if (t > 0)
            wait_parity_(cons_mb, ((uint32_t)(t - 1) >> 1) & 1);
        // re-arm the mbar this warp just consumed (next completion: step t+1)
        if (lane0)
            mbar_expect_tx_(cons_mb, TXR_BYTES);

        const float* hp = H + (1 - p) * H_STRIDE;

        float acc[NB][4];
#pragma unroll
        for (int b = 0; b < NB; b++)
#pragma unroll
            for (int j = 0; j < 4; j++) acc[b][j] = 0.f;

#pragma unroll
        for (int kk = 0; kk < 32; kk += 4) {
            const int k = kbase + kk;
            float4 hq[NB];
#pragma unroll
            for (int b = 0; b < NB; b++)
                hq[b] = *(const float4*)&hp[b * 512 + k];
#pragma unroll
            for (int j = 0; j < 4; j++) {
                const float4 w = w4[kk + j];
#pragma unroll
                for (int b = 0; b < NB; b++) {
                    const float hb = f4get(hq[b], j);
                    acc[b][0] = fmaf(hb, w.x, acc[b][0]);
                    acc[b][1] = fmaf(hb, w.y, acc[b][1]);
                    acc[b][2] = fmaf(hb, w.z, acc[b][2]);
                    acc[b][3] = fmaf(hb, w.w, acc[b][3]);
                }
            }
        }

        float* REDp = RED + p * (16 * 256);
#pragma unroll
        for (int b = 0; b < NB; b++) {
            *(float4*)&REDp[ks * 256 + b * 64 + (f4 << 2)] =
                make_float4(acc[b][0], acc[b][1], acc[b][2], acc[b][3]);
        }
        __syncthreads();

        float z0 = 0.f, z1 = 0.f, z2 = 0.f, z3 = 0.f;
#pragma unroll
        for (int s = 0; s < 16; s += 4) {
            z0 += REDp[(s + 0) * 256 + tid];
            z1 += REDp[(s + 1) * 256 + tid];
            z2 += REDp[(s + 2) * 256 + tid];
            z3 += REDp[(s + 3) * 256 + tid];
        }
        const float hv = tanhf(xpv + ((z0 + z1) + (z2 + z3)));

        if (t < TSTEPS - 1) {
            const uint32_t rb = (uint32_t)(p * H_BYTES);
            const uint32_t db = d_mb + (uint32_t)(p * 64);
#pragma unroll
            for (int r = 0; r < CLUSTER; r++)
                st_async_f32_(ra0[r] + rb, hv, ra0[r] + db);
        }
        xo_ptr[t * FDIM] = hv;
    }
}

// ----------------------------------------------------------------------------
extern "C" void kernel_launch(void* const* d_in, const int* in_sizes, int n_in,
                              void* d_out, int out_size)
{
    const float* inputs = (const float*)d_in[0];  // [64,1024,512]
    const float* w_ih   = (const float*)d_in[1];  // [512,512]
    const float* w_hh   = (const float*)d_in[2];  // [512,512]
    const float* bias   = (const float*)d_in[3];  // [512]
    float* out = (float*)d_out;                   // [64,1024,512]

    cudaFuncSetAttribute(xproj_mma_kernel,
                         cudaFuncAttributeMaxDynamicSharedMemorySize, XP_SMEM);
    cudaFuncSetAttribute(rnn_scan_kernel2,
                         cudaFuncAttributeMaxDynamicSharedMemorySize, SMB_TOTAL);

    // Phase 0: split fp32 -> bf16 hi/lo scratch
    conv_A_kernel<<<((size_t)MTOT * DDIM) / (256 * 4), 256>>>(inputs);
    conv_W_kernel<<<(DDIM * FDIM) / (256 * 4), 256>>>(w_ih);

    // Phase 1: x_proj via split-bf16 tensor-core GEMM
    {
        dim3 grid(FDIM / 128, MTOT / 128);  // (4, 512)
        xproj_mma_kernel<<<grid, 256, XP_SMEM>>>(bias, out);
    }
    // Phase 2: sequential scan (clustered persistent kernel, per-rank mbars)
    {
        rnn_scan_kernel2<<<NCTA2, 256, SMB_TOTAL>>>(w_hh, out);
    }
}

// round 13
// speedup vs baseline: 1.4637x; 1.4637x over previous
#include <cuda_runtime.h>
#include <cuda_bf16.h>
#include <cstdint>

#define BATCH  64
#define TSTEPS 1024
#define DDIM   512
#define FDIM   512
#define MTOT   (BATCH * TSTEPS)   // 65536

#define CLUSTER 8
#define NB      4
#define FCHUNK  64
#define NCLUST  (BATCH / NB)
#define NCTA2   (NCLUST * CLUSTER)

// ---------------------------------------------------------------------------
// Split-bf16 scratch (device globals: allowed scratch, no allocation)
// ---------------------------------------------------------------------------
__device__ __nv_bfloat16 g_Ahi[(size_t)MTOT * DDIM];   // 64 MB
__device__ __nv_bfloat16 g_Alo[(size_t)MTOT * DDIM];   // 64 MB
__device__ __nv_bfloat16 g_Whi[DDIM * FDIM];           // 512 KB
__device__ __nv_bfloat16 g_Wlo[DDIM * FDIM];           // 512 KB

__device__ __forceinline__ void split2_(float v, unsigned short& h, unsigned short& l) {
    __nv_bfloat16 hb = __float2bfloat16_rn(v);
    __nv_bfloat16 lb = __float2bfloat16_rn(v - __bfloat162float(hb));
    h = __bfloat16_as_ushort(hb);
    l = __bfloat16_as_ushort(lb);
}

__global__ __launch_bounds__(256) void conv_A_kernel(const float* __restrict__ in) {
    size_t i = ((size_t)blockIdx.x * blockDim.x + threadIdx.x) * 4;
    float4 v = *(const float4*)(in + i);
    unsigned short h0, h1, h2, h3, l0, l1, l2, l3;
    split2_(v.x, h0, l0); split2_(v.y, h1, l1);
    split2_(v.z, h2, l2); split2_(v.w, h3, l3);
    uint2 ph = make_uint2((uint32_t)h0 | ((uint32_t)h1 << 16),
                          (uint32_t)h2 | ((uint32_t)h3 << 16));
    uint2 pl = make_uint2((uint32_t)l0 | ((uint32_t)l1 << 16),
                          (uint32_t)l2 | ((uint32_t)l3 << 16));
    *(uint2*)(g_Ahi + i) = ph;
    *(uint2*)(g_Alo + i) = pl;
}

__global__ __launch_bounds__(256) void conv_W_kernel(const float* __restrict__ in) {
    size_t i = ((size_t)blockIdx.x * blockDim.x + threadIdx.x) * 4;
    float4 v = *(const float4*)(in + i);
    unsigned short h0, h1, h2, h3, l0, l1, l2, l3;
    split2_(v.x, h0, l0); split2_(v.y, h1, l1);
    split2_(v.z, h2, l2); split2_(v.w, h3, l3);
    uint2 ph = make_uint2((uint32_t)h0 | ((uint32_t)h1 << 16),
                          (uint32_t)h2 | ((uint32_t)h3 << 16));
    uint2 pl = make_uint2((uint32_t)l0 | ((uint32_t)l1 << 16),
                          (uint32_t)l2 | ((uint32_t)l3 << 16));
    *(uint2*)(g_Whi + i) = ph;
    *(uint2*)(g_Wlo + i) = pl;
}

// ---------------------------------------------------------------------------
// Phase 1: x_proj = A @ W + bias via split-bf16 HMMA (3 products, fp32 acc)
// CTA tile 128x128, K-tile 64; 8 warps 4(M)x2(N), warp tile 32x64.
// Round 12: EXACT round-10 structure (2-stage cp.async), ONLY the 12-MMA
// issue order changed to spacing-4 accumulator reuse (bitwise-same math).
// ---------------------------------------------------------------------------
#define XA_STRIDE 72
#define XB_STRIDE 136
#define OFF_AHI 0
#define OFF_ALO 18432
#define OFF_BHI 36864
#define OFF_BLO 54272
#define XP_STAGE 71680
#define XP_SMEM  (2 * XP_STAGE)   // 143360

__device__ __forceinline__ void ldsm4_(uint32_t* r, uint32_t addr) {
    asm volatile("ldmatrix.sync.aligned.m8n8.x4.shared.b16 {%0,%1,%2,%3}, [%4];"
                 : "=r"(r[0]), "=r"(r[1]), "=r"(r[2]), "=r"(r[3]) : "r"(addr));
}
__device__ __forceinline__ void ldsm4t_(uint32_t* r, uint32_t addr) {
    asm volatile("ldmatrix.sync.aligned.m8n8.x4.trans.shared.b16 {%0,%1,%2,%3}, [%4];"
                 : "=r"(r[0]), "=r"(r[1]), "=r"(r[2]), "=r"(r[3]) : "r"(addr));
}
__device__ __forceinline__ void mma16816_(float* d, const uint32_t* a,
                                          uint32_t b0, uint32_t b1) {
    asm volatile(
        "mma.sync.aligned.m16n8k16.row.col.f32.bf16.bf16.f32 "
        "{%0,%1,%2,%3}, {%4,%5,%6,%7}, {%8,%9}, {%0,%1,%2,%3};"
        : "+f"(d[0]), "+f"(d[1]), "+f"(d[2]), "+f"(d[3])
        : "r"(a[0]), "r"(a[1]), "r"(a[2]), "r"(a[3]), "r"(b0), "r"(b1));
}
__device__ __forceinline__ void cpasync16_(uint32_t s, const void* g) {
    asm volatile("cp.async.cg.shared.global [%0], [%1], 16;"
                 :: "r"(s), "l"(g) : "memory");
}

extern __shared__ char xsmem[];

__global__ __launch_bounds__(256, 1) void xproj_mma_kernel(
    const float* __restrict__ bias,  // [512]
    float* __restrict__ C)           // [65536, 512]
{
    const int tid  = threadIdx.x;
    const int lane = tid & 31;
    const int wid  = tid >> 5;
    const int m0 = blockIdx.y * 128;
    const int n0 = blockIdx.x * 128;
    const int m_w = (wid >> 1) * 32;   // warp M offset in tile
    const int n_w = (wid & 1) * 64;    // warp N offset in tile

    uint32_t sm;
    asm("{ .reg .u64 t; cvta.to.shared.u64 t, %1; cvt.u32.u64 %0, t; }"
        : "=r"(sm) : "l"(xsmem));

    // ldmatrix lane addressing (canonical m16n8k16 mapping)
    const int a_row   = (lane & 15);
    const int a_khalf = (lane >> 4) & 1;
    const int b_krow  = (lane & 7) + (((lane >> 3) & 1) << 3);
    const int b_ncol8 = ((lane >> 4) & 1) << 3;

    // stage-relative fragment byte offsets
    uint32_t aHiR[2], aLoR[2];
#pragma unroll
    for (int mt = 0; mt < 2; mt++) {
        const uint32_t rb =
            (uint32_t)(((m_w + mt * 16 + a_row) * XA_STRIDE + a_khalf * 8) * 2);
        aHiR[mt] = OFF_AHI + rb;
        aLoR[mt] = OFF_ALO + rb;
    }
    const uint32_t bRel = (uint32_t)((b_krow * XB_STRIDE + n_w + b_ncol8) * 2);
    const uint32_t bHiR = OFF_BHI + bRel;
    const uint32_t bLoR = OFF_BLO + bRel;

    float acc[2][8][4];
#pragma unroll
    for (int mt = 0; mt < 2; mt++)
#pragma unroll
        for (int nt = 0; nt < 8; nt++)
#pragma unroll
            for (int q = 0; q < 4; q++) acc[mt][nt][q] = 0.f;

    // tile loader: issue cp.asyncs for K-tile kt into stage s
    auto load_tile = [&](int kt, int s) {
        const uint32_t stage = sm + (uint32_t)(s * XP_STAGE);
#pragma unroll
        for (int it = 0; it < 4; it++) {
            const int idx = tid + it * 256;
            const int r = idx >> 3, c8 = (idx & 7) << 3;
            const size_t g = (size_t)(m0 + r) * DDIM + kt * 64 + c8;
            const uint32_t so = (uint32_t)((r * XA_STRIDE + c8) * 2);
            cpasync16_(stage + OFF_AHI + so, g_Ahi + g);
            cpasync16_(stage + OFF_ALO + so, g_Alo + g);
        }
#pragma unroll
        for (int it = 0; it < 4; it++) {
            const int idx = tid + it * 256;
            const int r = idx >> 4, c8 = (idx & 15) << 3;
            const size_t g = (size_t)(kt * 64 + r) * FDIM + n0 + c8;
            const uint32_t so = (uint32_t)((r * XB_STRIDE + c8) * 2);
            cpasync16_(stage + OFF_BHI + so, g_Whi + g);
            cpasync16_(stage + OFF_BLO + so, g_Wlo + g);
        }
        asm volatile("cp.async.commit_group;" ::: "memory");
    };

    load_tile(0, 0);

#pragma unroll 1
    for (int kt = 0; kt < DDIM / 64; kt++) {
        if (kt < DDIM / 64 - 1) {
            load_tile(kt + 1, (kt + 1) & 1);
            asm volatile("cp.async.wait_group 1;" ::: "memory");
        } else {
            asm volatile("cp.async.wait_group 0;" ::: "memory");
        }
        __syncthreads();

        const uint32_t stage = sm + (uint32_t)((kt & 1) * XP_STAGE);
#pragma unroll
        for (int kc = 0; kc < 4; kc++) {
            uint32_t ah[2][4], al[2][4];
            ldsm4_(ah[0], stage + aHiR[0] + kc * 32);
            ldsm4_(ah[1], stage + aHiR[1] + kc * 32);
            ldsm4_(al[0], stage + aLoR[0] + kc * 32);
            ldsm4_(al[1], stage + aLoR[1] + kc * 32);
            const uint32_t kOff = (uint32_t)(kc * 16 * XB_STRIDE * 2);
#pragma unroll
            for (int nt16 = 0; nt16 < 4; nt16++) {
                uint32_t bh[4], bl[4];
                ldsm4t_(bh, stage + bHiR + kOff + nt16 * 32);
                ldsm4t_(bl, stage + bLoR + kOff + nt16 * 32);
                float* d00 = acc[0][2 * nt16];
                float* d01 = acc[0][2 * nt16 + 1];
                float* d10 = acc[1][2 * nt16];
                float* d11 = acc[1][2 * nt16 + 1];
                // spacing-4 accumulator reuse; per-accumulator contribution
                // order identical to round 10 (bitwise-same result):
                //   d00: ah0*bh01, ah0*bl01, al0*bh01
                //   d01: ah0*bh23, ah0*bl23, al0*bh23
                //   d10: ah1*bh01, ah1*bl01, al1*bh01
                //   d11: ah1*bh23, ah1*bl23, al1*bh23
                mma16816_(d00, ah[0], bh[0], bh[1]);
                mma16816_(d01, ah[0], bh[2], bh[3]);
                mma16816_(d10, ah[1], bh[0], bh[1]);
                mma16816_(d11, ah[1], bh[2], bh[3]);
                mma16816_(d00, ah[0], bl[0], bl[1]);
                mma16816_(d01, ah[0], bl[2], bl[3]);
                mma16816_(d10, ah[1], bl[0], bl[1]);
                mma16816_(d11, ah[1], bl[2], bl[3]);
                mma16816_(d00, al[0], bh[0], bh[1]);
                mma16816_(d01, al[0], bh[2], bh[3]);
                mma16816_(d10, al[1], bh[0], bh[1]);
                mma16816_(d11, al[1], bh[2], bh[3]);
            }
        }
        __syncthreads();
    }

    // epilogue: c0,c1 -> row g, cols tg*2,+1 ; c2,c3 -> row g+8
    const int g  = lane >> 2;
    const int tg = lane & 3;
#pragma unroll
    for (int mt = 0; mt < 2; mt++) {
#pragma unroll
        for (int nt = 0; nt < 8; nt++) {
            const int row = m0 + m_w + mt * 16 + g;
            const int col = n0 + n_w + nt * 8 + tg * 2;
            const float2 b2 = *(const float2*)&bias[col];
            *(float2*)&C[(size_t)row * FDIM + col] =
                make_float2(acc[mt][nt][0] + b2.x, acc[mt][nt][1] + b2.y);
            *(float2*)&C[(size_t)(row + 8) * FDIM + col] =
                make_float2(acc[mt][nt][2] + b2.x, acc[mt][nt][3] + b2.y);
        }
    }
}

// ----------------------------------------------------------------------------
// Phase 2: sequential scan (round-8/10 version, byte-for-byte — known good)
// ----------------------------------------------------------------------------
#define SMB_RED   16384
#define SMB_MBAR  49152
#define SMB_TOTAL 49184
#define H_STRIDE  (NB * 512)
#define H_BYTES   (NB * 512 * 4)
#define TX_BYTES  (CLUSTER * 256 * 4)

__device__ __forceinline__ void cluster_sync_() {
    asm volatile("barrier.cluster.arrive.aligned;" ::: "memory");
    asm volatile("barrier.cluster.wait.aligned;" ::: "memory");
}
__device__ __forceinline__ void mbar_init_(uint32_t mbar, uint32_t cnt) {
    asm volatile("mbarrier.init.shared.b64 [%0], %1;" :: "r"(mbar), "r"(cnt)
                 : "memory");
}
__device__ __forceinline__ void mbar_expect_tx_(uint32_t mbar, uint32_t bytes) {
    asm volatile("mbarrier.arrive.expect_tx.shared.b64 _, [%0], %1;"
                 :: "r"(mbar), "r"(bytes) : "memory");
}
__device__ __forceinline__ void wait_parity_(uint32_t mbar, uint32_t phase) {
    asm volatile(
        "{\n\t"
        ".reg .pred P;\n\t"
        "WL%=:\n\t"
        "mbarrier.try_wait.parity.acquire.cluster.shared::cta.b64 P, [%0], %1, 0x989680;\n\t"
        "@P bra.uni WD%=;\n\t"
        "bra.uni WL%=;\n\t"
        "WD%=:\n\t"
        "}"
        :: "r"(mbar), "r"(phase) : "memory");
}
__device__ __forceinline__ void st_async_f32_(uint32_t raddr, float v,
                                              uint32_t rmbar) {
    asm volatile(
        "st.async.shared::cluster.mbarrier::complete_tx::bytes.b32 [%0], %1, [%2];"
        :: "r"(raddr), "r"(__float_as_uint(v)), "r"(rmbar) : "memory");
}
__device__ __forceinline__ float f4get(const float4 v, int j) {
    return j == 0 ? v.x : (j == 1 ? v.y : (j == 2 ? v.z : v.w));
}

extern __shared__ float smem2[];

__global__ __launch_bounds__(256, 1) __cluster_dims__(CLUSTER, 1, 1)
void rnn_scan_kernel(const float* __restrict__ w_hh,
                     float* __restrict__ xo)
{
    float* H   = smem2;
    float* RED = smem2 + SMB_RED / 4;

    const int tid  = threadIdx.x;
    const int rank = blockIdx.x % CLUSTER;
    const int bg   = blockIdx.x / CLUSTER;
    const int f0   = rank * FCHUNK;

    const int f4    = tid & 15;
    const int ks    = tid >> 4;
    const int kbase = ks * 32;
    const int ob = tid >> 6;
    const int of = tid & 63;
    float* xo_ptr = xo + (size_t)(bg * NB + ob) * TSTEPS * FDIM + f0 + of;

    float4 w4[32];
    {
        const float* wp = w_hh + (size_t)kbase * FDIM + f0 + (f4 << 2);
#pragma unroll
        for (int kk = 0; kk < 32; kk++)
            w4[kk] = *(const float4*)(wp + (size_t)kk * FDIM);
    }

    uint32_t sbase;
    asm("{ .reg .u64 t; cvta.to.shared.u64 t, %1; cvt.u32.u64 %0, t; }"
        : "=r"(sbase) : "l"(smem2));
    const uint32_t mbar0 = sbase + SMB_MBAR;

    if (tid == 0) {
        mbar_init_(mbar0, 1);
        mbar_init_(mbar0 + 8, 1);
    }
    for (int i = tid; i < H_STRIDE; i += 256) H[H_STRIDE + i] = 0.f;
    __syncthreads();
    if (tid == 0) mbar_expect_tx_(mbar0, TX_BYTES);
    cluster_sync_();

    const uint32_t h0_byte = (uint32_t)((ob * 512 + f0 + of) * 4);
    uint32_t ra0[CLUSTER];
#pragma unroll
    for (int r = 0; r < CLUSTER; r++) {
        asm("mapa.shared::cluster.u32 %0, %1, %2;"
            : "=r"(ra0[r]) : "r"(sbase + h0_byte), "r"(r));
    }
    const uint32_t d_mb = (uint32_t)SMB_MBAR - h0_byte;

#pragma unroll 1
    for (int t = 0; t < TSTEPS; t++) {
        const int p = t & 1;
        const float xpv = xo_ptr[t * FDIM];

        if (t > 0)
            wait_parity_(mbar0 + (1 - p) * 8, ((uint32_t)(t - 1) >> 1) & 1);
        if (tid == 0 && t < TSTEPS - 2)
            mbar_expect_tx_(mbar0 + (1 - p) * 8, TX_BYTES);

        const float* hp = H + (1 - p) * H_STRIDE;

        float acc[NB][4];
#pragma unroll
        for (int b = 0; b < NB; b++)
#pragma unroll
            for (int j = 0; j < 4; j++) acc[b][j] = 0.f;

#pragma unroll
        for (int kk = 0; kk < 32; kk += 4) {
            const int k = kbase + kk;
            float4 hq[NB];
#pragma unroll
            for (int b = 0; b < NB; b++)
                hq[b] = *(const float4*)&hp[b * 512 + k];
#pragma unroll
            for (int j = 0; j < 4; j++) {
                const float4 w = w4[kk + j];
#pragma unroll
                for (int b = 0; b < NB; b++) {
                    const float hb = f4get(hq[b], j);
                    acc[b][0] = fmaf(hb, w.x, acc[b][0]);
                    acc[b][1] = fmaf(hb, w.y, acc[b][1]);
                    acc[b][2] = fmaf(hb, w.z, acc[b][2]);
                    acc[b][3] = fmaf(hb, w.w, acc[b][3]);
                }
            }
        }

        float* REDp = RED + p * (16 * 256);
#pragma unroll
        for (int b = 0; b < NB; b++) {
            *(float4*)&REDp[ks * 256 + b * 64 + (f4 << 2)] =
                make_float4(acc[b][0], acc[b][1], acc[b][2], acc[b][3]);
        }
        __syncthreads();

        float z0 = 0.f, z1 = 0.f, z2 = 0.f, z3 = 0.f;
#pragma unroll
        for (int s = 0; s < 16; s += 4) {
            z0 += REDp[(s + 0) * 256 + tid];
            z1 += REDp[(s + 1) * 256 + tid];
            z2 += REDp[(s + 2) * 256 + tid];
            z3 += REDp[(s + 3) * 256 + tid];
        }
        const float hv = tanhf(xpv + ((z0 + z1) + (z2 + z3)));

        xo_ptr[t * FDIM] = hv;

        if (t < TSTEPS - 1) {
            const uint32_t rb = (uint32_t)(p * H_BYTES);
            const uint32_t db = d_mb + (uint32_t)(p * 8);
#pragma unroll
            for (int r = 0; r < CLUSTER; r++)
                st_async_f32_(ra0[r] + rb, hv, ra0[r] + db);
        }
    }
}

// ----------------------------------------------------------------------------
extern "C" void kernel_launch(void* const* d_in, const int* in_sizes, int n_in,
                              void* d_out, int out_size)
{
    const float* inputs = (const float*)d_in[0];  // [64,1024,512]
    const float* w_ih   = (const float*)d_in[1];  // [512,512]
    const float* w_hh   = (const float*)d_in[2];  // [512,512]
    const float* bias   = (const float*)d_in[3];  // [512]
    float* out = (float*)d_out;                   // [64,1024,512]

    cudaFuncSetAttribute(xproj_mma_kernel,
                         cudaFuncAttributeMaxDynamicSharedMemorySize, XP_SMEM);
    cudaFuncSetAttribute(rnn_scan_kernel,
                         cudaFuncAttributeMaxDynamicSharedMemorySize, SMB_TOTAL);

    // Phase 0: split fp32 -> bf16 hi/lo scratch
    conv_A_kernel<<<((size_t)MTOT * DDIM) / (256 * 4), 256>>>(inputs);
    conv_W_kernel<<<(DDIM * FDIM) / (256 * 4), 256>>>(w_ih);

    // Phase 1: x_proj via split-bf16 tensor-core GEMM
    {
        dim3 grid(FDIM / 128, MTOT / 128);  // (4, 512)
        xproj_mma_kernel<<<grid, 256, XP_SMEM>>>(bias, out);
    }
    // Phase 2: sequential scan (clustered persistent kernel)
    {
        rnn_scan_kernel<<<NCTA2, 256, SMB_TOTAL>>>(w_hh, out);
    }
}

// round 15
// speedup vs baseline: 1.4916x; 1.0190x over previous
#include <cuda_runtime.h>
#include <cuda_bf16.h>
#include <cstdint>

#define BATCH  64
#define TSTEPS 1024
#define DDIM   512
#define FDIM   512
#define MTOT   (BATCH * TSTEPS)   // 65536

#define CLUSTER 8
#define NB      4
#define FCHUNK  64
#define NCLUST  (BATCH / NB)
#define NCTA2   (NCLUST * CLUSTER)

typedef unsigned long long ull;

// ---------------------------------------------------------------------------
// Split-bf16 scratch (device globals: allowed scratch, no allocation)
// ---------------------------------------------------------------------------
__device__ __nv_bfloat16 g_Ahi[(size_t)MTOT * DDIM];   // 64 MB
__device__ __nv_bfloat16 g_Alo[(size_t)MTOT * DDIM];   // 64 MB
__device__ __nv_bfloat16 g_Whi[DDIM * FDIM];           // 512 KB
__device__ __nv_bfloat16 g_Wlo[DDIM * FDIM];           // 512 KB

__device__ __forceinline__ void split2_(float v, unsigned short& h, unsigned short& l) {
    __nv_bfloat16 hb = __float2bfloat16_rn(v);
    __nv_bfloat16 lb = __float2bfloat16_rn(v - __bfloat162float(hb));
    h = __bfloat16_as_ushort(hb);
    l = __bfloat16_as_ushort(lb);
}

__global__ __launch_bounds__(256) void conv_A_kernel(const float* __restrict__ in) {
    size_t i = ((size_t)blockIdx.x * blockDim.x + threadIdx.x) * 4;
    float4 v = *(const float4*)(in + i);
    unsigned short h0, h1, h2, h3, l0, l1, l2, l3;
    split2_(v.x, h0, l0); split2_(v.y, h1, l1);
    split2_(v.z, h2, l2); split2_(v.w, h3, l3);
    uint2 ph = make_uint2((uint32_t)h0 | ((uint32_t)h1 << 16),
                          (uint32_t)h2 | ((uint32_t)h3 << 16));
    uint2 pl = make_uint2((uint32_t)l0 | ((uint32_t)l1 << 16),
                          (uint32_t)l2 | ((uint32_t)l3 << 16));
    *(uint2*)(g_Ahi + i) = ph;
    *(uint2*)(g_Alo + i) = pl;
}

__global__ __launch_bounds__(256) void conv_W_kernel(const float* __restrict__ in) {
    size_t i = ((size_t)blockIdx.x * blockDim.x + threadIdx.x) * 4;
    float4 v = *(const float4*)(in + i);
    unsigned short h0, h1, h2, h3, l0, l1, l2, l3;
    split2_(v.x, h0, l0); split2_(v.y, h1, l1);
    split2_(v.z, h2, l2); split2_(v.w, h3, l3);
    uint2 ph = make_uint2((uint32_t)h0 | ((uint32_t)h1 << 16),
                          (uint32_t)h2 | ((uint32_t)h3 << 16));
    uint2 pl = make_uint2((uint32_t)l0 | ((uint32_t)l1 << 16),
                          (uint32_t)l2 | ((uint32_t)l3 << 16));
    *(uint2*)(g_Whi + i) = ph;
    *(uint2*)(g_Wlo + i) = pl;
}

// ---------------------------------------------------------------------------
// Phase 1: x_proj = A @ W + bias via split-bf16 HMMA (3 products, fp32 acc)
// (round-12/13 version, byte-for-byte — known good, 2742 us total)
// ---------------------------------------------------------------------------
#define XA_STRIDE 72
#define XB_STRIDE 136
#define OFF_AHI 0
#define OFF_ALO 18432
#define OFF_BHI 36864
#define OFF_BLO 54272
#define XP_STAGE 71680
#define XP_SMEM  (2 * XP_STAGE)   // 143360

__device__ __forceinline__ void ldsm4_(uint32_t* r, uint32_t addr) {
    asm volatile("ldmatrix.sync.aligned.m8n8.x4.shared.b16 {%0,%1,%2,%3}, [%4];"
                 : "=r"(r[0]), "=r"(r[1]), "=r"(r[2]), "=r"(r[3]) : "r"(addr));
}
__device__ __forceinline__ void ldsm4t_(uint32_t* r, uint32_t addr) {
    asm volatile("ldmatrix.sync.aligned.m8n8.x4.trans.shared.b16 {%0,%1,%2,%3}, [%4];"
                 : "=r"(r[0]), "=r"(r[1]), "=r"(r[2]), "=r"(r[3]) : "r"(addr));
}
__device__ __forceinline__ void mma16816_(float* d, const uint32_t* a,
                                          uint32_t b0, uint32_t b1) {
    asm volatile(
        "mma.sync.aligned.m16n8k16.row.col.f32.bf16.bf16.f32 "
        "{%0,%1,%2,%3}, {%4,%5,%6,%7}, {%8,%9}, {%0,%1,%2,%3};"
        : "+f"(d[0]), "+f"(d[1]), "+f"(d[2]), "+f"(d[3])
        : "r"(a[0]), "r"(a[1]), "r"(a[2]), "r"(a[3]), "r"(b0), "r"(b1));
}
__device__ __forceinline__ void cpasync16_(uint32_t s, const void* g) {
    asm volatile("cp.async.cg.shared.global [%0], [%1], 16;"
                 :: "r"(s), "l"(g) : "memory");
}

extern __shared__ char xsmem[];

__global__ __launch_bounds__(256, 1) void xproj_mma_kernel(
    const float* __restrict__ bias,  // [512]
    float* __restrict__ C)           // [65536, 512]
{
    const int tid  = threadIdx.x;
    const int lane = tid & 31;
    const int wid  = tid >> 5;
    const int m0 = blockIdx.y * 128;
    const int n0 = blockIdx.x * 128;
    const int m_w = (wid >> 1) * 32;   // warp M offset in tile
    const int n_w = (wid & 1) * 64;    // warp N offset in tile

    uint32_t sm;
    asm("{ .reg .u64 t; cvta.to.shared.u64 t, %1; cvt.u32.u64 %0, t; }"
        : "=r"(sm) : "l"(xsmem));

    const int a_row   = (lane & 15);
    const int a_khalf = (lane >> 4) & 1;
    const int b_krow  = (lane & 7) + (((lane >> 3) & 1) << 3);
    const int b_ncol8 = ((lane >> 4) & 1) << 3;

    uint32_t aHiR[2], aLoR[2];
#pragma unroll
    for (int mt = 0; mt < 2; mt++) {
        const uint32_t rb =
            (uint32_t)(((m_w + mt * 16 + a_row) * XA_STRIDE + a_khalf * 8) * 2);
        aHiR[mt] = OFF_AHI + rb;
        aLoR[mt] = OFF_ALO + rb;
    }
    const uint32_t bRel = (uint32_t)((b_krow * XB_STRIDE + n_w + b_ncol8) * 2);
    const uint32_t bHiR = OFF_BHI + bRel;
    const uint32_t bLoR = OFF_BLO + bRel;

    float acc[2][8][4];
#pragma unroll
    for (int mt = 0; mt < 2; mt++)
#pragma unroll
        for (int nt = 0; nt < 8; nt++)
#pragma unroll
            for (int q = 0; q < 4; q++) acc[mt][nt][q] = 0.f;

    auto load_tile = [&](int kt, int s) {
        const uint32_t stage = sm + (uint32_t)(s * XP_STAGE);
#pragma unroll
        for (int it = 0; it < 4; it++) {
            const int idx = tid + it * 256;
            const int r = idx >> 3, c8 = (idx & 7) << 3;
            const size_t g = (size_t)(m0 + r) * DDIM + kt * 64 + c8;
            const uint32_t so = (uint32_t)((r * XA_STRIDE + c8) * 2);
            cpasync16_(stage + OFF_AHI + so, g_Ahi + g);
            cpasync16_(stage + OFF_ALO + so, g_Alo + g);
        }
#pragma unroll
        for (int it = 0; it < 4; it++) {
            const int idx = tid + it * 256;
            const int r = idx >> 4, c8 = (idx & 15) << 3;
            const size_t g = (size_t)(kt * 64 + r) * FDIM + n0 + c8;
            const uint32_t so = (uint32_t)((r * XB_STRIDE + c8) * 2);
            cpasync16_(stage + OFF_BHI + so, g_Whi + g);
            cpasync16_(stage + OFF_BLO + so, g_Wlo + g);
        }
        asm volatile("cp.async.commit_group;" ::: "memory");
    };

    load_tile(0, 0);

#pragma unroll 1
    for (int kt = 0; kt < DDIM / 64; kt++) {
        if (kt < DDIM / 64 - 1) {
            load_tile(kt + 1, (kt + 1) & 1);
            asm volatile("cp.async.wait_group 1;" ::: "memory");
        } else {
            asm volatile("cp.async.wait_group 0;" ::: "memory");
        }
        __syncthreads();

        const uint32_t stage = sm + (uint32_t)((kt & 1) * XP_STAGE);
#pragma unroll
        for (int kc = 0; kc < 4; kc++) {
            uint32_t ah[2][4], al[2][4];
            ldsm4_(ah[0], stage + aHiR[0] + kc * 32);
            ldsm4_(ah[1], stage + aHiR[1] + kc * 32);
            ldsm4_(al[0], stage + aLoR[0] + kc * 32);
            ldsm4_(al[1], stage + aLoR[1] + kc * 32);
            const uint32_t kOff = (uint32_t)(kc * 16 * XB_STRIDE * 2);
#pragma unroll
            for (int nt16 = 0; nt16 < 4; nt16++) {
                uint32_t bh[4], bl[4];
                ldsm4t_(bh, stage + bHiR + kOff + nt16 * 32);
                ldsm4t_(bl, stage + bLoR + kOff + nt16 * 32);
                float* d00 = acc[0][2 * nt16];
                float* d01 = acc[0][2 * nt16 + 1];
                float* d10 = acc[1][2 * nt16];
                float* d11 = acc[1][2 * nt16 + 1];
                mma16816_(d00, ah[0], bh[0], bh[1]);
                mma16816_(d01, ah[0], bh[2], bh[3]);
                mma16816_(d10, ah[1], bh[0], bh[1]);
                mma16816_(d11, ah[1], bh[2], bh[3]);
                mma16816_(d00, ah[0], bl[0], bl[1]);
                mma16816_(d01, ah[0], bl[2], bl[3]);
                mma16816_(d10, ah[1], bl[0], bl[1]);
                mma16816_(d11, ah[1], bl[2], bl[3]);
                mma16816_(d00, al[0], bh[0], bh[1]);
                mma16816_(d01, al[0], bh[2], bh[3]);
                mma16816_(d10, al[1], bh[0], bh[1]);
                mma16816_(d11, al[1], bh[2], bh[3]);
            }
        }
        __syncthreads();
    }

    const int g  = lane >> 2;
    const int tg = lane & 3;
#pragma unroll
    for (int mt = 0; mt < 2; mt++) {
#pragma unroll
        for (int nt = 0; nt < 8; nt++) {
            const int row = m0 + m_w + mt * 16 + g;
            const int col = n0 + n_w + nt * 8 + tg * 2;
            const float2 b2 = *(const float2*)&bias[col];
            *(float2*)&C[(size_t)row * FDIM + col] =
                make_float2(acc[mt][nt][0] + b2.x, acc[mt][nt][1] + b2.y);
            *(float2*)&C[(size_t)(row + 8) * FDIM + col] =
                make_float2(acc[mt][nt][2] + b2.x, acc[mt][nt][3] + b2.y);
        }
    }
}

// ----------------------------------------------------------------------------
// Phase 2: sequential scan (round-8 structure). ONE change vs round 13:
// the inner GEMV uses packed fma.rn.f32x2 (bitwise-identical fp32 math;
// halves FMA-pipe issue count 512 -> 256 warp-instr per thread-step).
// ----------------------------------------------------------------------------
#define SMB_RED   16384
#define SMB_MBAR  49152
#define SMB_TOTAL 49184
#define H_STRIDE  (NB * 512)
#define H_BYTES   (NB * 512 * 4)
#define TX_BYTES  (CLUSTER * 256 * 4)

__device__ __forceinline__ void cluster_sync_() {
    asm volatile("barrier.cluster.arrive.aligned;" ::: "memory");
    asm volatile("barrier.cluster.wait.aligned;" ::: "memory");
}
__device__ __forceinline__ void mbar_init_(uint32_t mbar, uint32_t cnt) {
    asm volatile("mbarrier.init.shared.b64 [%0], %1;" :: "r"(mbar), "r"(cnt)
                 : "memory");
}
__device__ __forceinline__ void mbar_expect_tx_(uint32_t mbar, uint32_t bytes) {
    asm volatile("mbarrier.arrive.expect_tx.shared.b64 _, [%0], %1;"
                 :: "r"(mbar), "r"(bytes) : "memory");
}
__device__ __forceinline__ void wait_parity_(uint32_t mbar, uint32_t phase) {
    asm volatile(
        "{\n\t"
        ".reg .pred P;\n\t"
        "WL%=:\n\t"
        "mbarrier.try_wait.parity.acquire.cluster.shared::cta.b64 P, [%0], %1, 0x989680;\n\t"
        "@P bra.uni WD%=;\n\t"
        "bra.uni WL%=;\n\t"
        "WD%=:\n\t"
        "}"
        :: "r"(mbar), "r"(phase) : "memory");
}
__device__ __forceinline__ void st_async_f32_(uint32_t raddr, float v,
                                              uint32_t rmbar) {
    asm volatile(
        "st.async.shared::cluster.mbarrier::complete_tx::bytes.b32 [%0], %1, [%2];"
        :: "r"(raddr), "r"(__float_as_uint(v)), "r"(rmbar) : "memory");
}
__device__ __forceinline__ float f4get(const float4 v, int j) {
    return j == 0 ? v.x : (j == 1 ? v.y : (j == 2 ? v.z : v.w));
}
// packed fp32x2 helpers (compile-verified on this toolchain in round 6)
__device__ __forceinline__ ull fma2x_(ull a, ull b, ull c) {
    ull d;
    asm("fma.rn.f32x2 %0, %1, %2, %3;" : "=l"(d) : "l"(a), "l"(b), "l"(c));
    return d;
}
__device__ __forceinline__ ull splat2x_(float x) {
    ull d;
    unsigned u = __float_as_uint(x);
    asm("mov.b64 %0, {%1, %1};" : "=l"(d) : "r"(u));
    return d;
}

extern __shared__ float smem2[];

__global__ __launch_bounds__(256, 1) __cluster_dims__(CLUSTER, 1, 1)
void rnn_scan_kernel(const float* __restrict__ w_hh,
                     float* __restrict__ xo)
{
    float* H   = smem2;
    float* RED = smem2 + SMB_RED / 4;

    const int tid  = threadIdx.x;
    const int rank = blockIdx.x % CLUSTER;
    const int bg   = blockIdx.x / CLUSTER;
    const int f0   = rank * FCHUNK;

    const int f4    = tid & 15;
    const int ks    = tid >> 4;
    const int kbase = ks * 32;
    const int ob = tid >> 6;
    const int of = tid & 63;
    float* xo_ptr = xo + (size_t)(bg * NB + ob) * TSTEPS * FDIM + f0 + of;

    // Register-cached W tile as packed f32x2 pairs:
    // w2[kk].x = (W[f+0], W[f+1]), w2[kk].y = (W[f+2], W[f+3])
    ulonglong2 w2[32];
    {
        const float* wp = w_hh + (size_t)kbase * FDIM + f0 + (f4 << 2);
#pragma unroll
        for (int kk = 0; kk < 32; kk++)
            w2[kk] = *(const ulonglong2*)(wp + (size_t)kk * FDIM);
    }

    uint32_t sbase;
    asm("{ .reg .u64 t; cvta.to.shared.u64 t, %1; cvt.u32.u64 %0, t; }"
        : "=r"(sbase) : "l"(smem2));
    const uint32_t mbar0 = sbase + SMB_MBAR;

    if (tid == 0) {
        mbar_init_(mbar0, 1);
        mbar_init_(mbar0 + 8, 1);
    }
    for (int i = tid; i < H_STRIDE; i += 256) H[H_STRIDE + i] = 0.f;
    __syncthreads();
    if (tid == 0) mbar_expect_tx_(mbar0, TX_BYTES);
    cluster_sync_();

    const uint32_t h0_byte = (uint32_t)((ob * 512 + f0 + of) * 4);
    uint32_t ra0[CLUSTER];
#pragma unroll
    for (int r = 0; r < CLUSTER; r++) {
        asm("mapa.shared::cluster.u32 %0, %1, %2;"
            : "=r"(ra0[r]) : "r"(sbase + h0_byte), "r"(r));
    }
    const uint32_t d_mb = (uint32_t)SMB_MBAR - h0_byte;

#pragma unroll 1
    for (int t = 0; t < TSTEPS; t++) {
        const int p = t & 1;
        const float xpv = xo_ptr[t * FDIM];

        if (t > 0)
            wait_parity_(mbar0 + (1 - p) * 8, ((uint32_t)(t - 1) >> 1) & 1);
        if (tid == 0 && t < TSTEPS - 2)
            mbar_expect_tx_(mbar0 + (1 - p) * 8, TX_BYTES);

        const float* hp = H + (1 - p) * H_STRIDE;

        ull acc2[NB][2];
#pragma unroll
        for (int b = 0; b < NB; b++) { acc2[b][0] = 0ull; acc2[b][1] = 0ull; }

#pragma unroll
        for (int kk = 0; kk < 32; kk += 4) {
            const int k = kbase + kk;
            float4 hq[NB];
#pragma unroll
            for (int b = 0; b < NB; b++)
                hq[b] = *(const float4*)&hp[b * 512 + k];
#pragma unroll
            for (int j = 0; j < 4; j++) {
                const ulonglong2 wv = w2[kk + j];
#pragma unroll
                for (int b = 0; b < NB; b++) {
                    const ull h2 = splat2x_(f4get(hq[b], j));
                    acc2[b][0] = fma2x_(h2, wv.x, acc2[b][0]);
                    acc2[b][1] = fma2x_(h2, wv.y, acc2[b][1]);
                }
            }
        }

        // bytes identical to the float4 store of {acc[0..3]}
        float* REDp = RED + p * (16 * 256);
#pragma unroll
        for (int b = 0; b < NB; b++) {
            *(ulonglong2*)&REDp[ks * 256 + b * 64 + (f4 << 2)] =
                make_ulonglong2(acc2[b][0], acc2[b][1]);
        }
        __syncthreads();

        float z0 = 0.f, z1 = 0.f, z2 = 0.f, z3 = 0.f;
#pragma unroll
        for (int s = 0; s < 16; s += 4) {
            z0 += REDp[(s + 0) * 256 + tid];
            z1 += REDp[(s + 1) * 256 + tid];
            z2 += REDp[(s + 2) * 256 + tid];
            z3 += REDp[(s + 3) * 256 + tid];
        }
        const float hv = tanhf(xpv + ((z0 + z1) + (z2 + z3)));

        xo_ptr[t * FDIM] = hv;

        if (t < TSTEPS - 1) {
            const uint32_t rb = (uint32_t)(p * H_BYTES);
            const uint32_t db = d_mb + (uint32_t)(p * 8);
#pragma unroll
            for (int r = 0; r < CLUSTER; r++)
                st_async_f32_(ra0[r] + rb, hv, ra0[r] + db);
        }
    }
}

// ----------------------------------------------------------------------------
extern "C" void kernel_launch(void* const* d_in, const int* in_sizes, int n_in,
                              void* d_out, int out_size)
{
    const float* inputs = (const float*)d_in[0];  // [64,1024,512]
    const float* w_ih   = (const float*)d_in[1];  // [512,512]
    const float* w_hh   = (const float*)d_in[2];  // [512,512]
    const float* bias   = (const float*)d_in[3];  // [512]
    float* out = (float*)d_out;                   // [64,1024,512]

    cudaFuncSetAttribute(xproj_mma_kernel,
                         cudaFuncAttributeMaxDynamicSharedMemorySize, XP_SMEM);
    cudaFuncSetAttribute(rnn_scan_kernel,
                         cudaFuncAttributeMaxDynamicSharedMemorySize, SMB_TOTAL);

    // Phase 0: split fp32 -> bf16 hi/lo scratch
    conv_A_kernel<<<((size_t)MTOT * DDIM) / (256 * 4), 256>>>(inputs);
    conv_W_kernel<<<(DDIM * FDIM) / (256 * 4), 256>>>(w_ih);

    // Phase 1: x_proj via split-bf16 tensor-core GEMM
    {
        dim3 grid(FDIM / 128, MTOT / 128);  // (4, 512)
        xproj_mma_kernel<<<grid, 256, XP_SMEM>>>(bias, out);
    }
    // Phase 2: sequential scan (clustered persistent kernel)
    {
        rnn_scan_kernel<<<NCTA2, 256, SMB_TOTAL>>>(w_hh, out);
    }
}